// round 6
// baseline (speedup 1.0000x reference)
#include <cuda_runtime.h>
#include <cstdint>
#include <math.h>

// Problem dims
#define Bsz   4
#define Lsz   2048
#define Esz   1024
#define Hh    16
#define DHsz  64
#define HIDs  1024
#define Msz   (Bsz*Lsz)     // 8192 rows
#define FFs   (4*HIDs)      // 4096

// ---------------- scratch (no allocs allowed -> __device__ globals) ----------
__device__ float g_a   [Msz*(size_t)HIDs];
__device__ float g_b   [Msz*(size_t)HIDs];      // b, becomes h after scan
__device__ float g_d   [Msz*(size_t)HIDs];
__device__ float g_z   [Msz*(size_t)HIDs];
__device__ float g_u   [Msz*(size_t)HIDs];
__device__ float g_mid [(size_t)Msz*FFs];
__device__ float g_v   [Msz*(size_t)HIDs];
__device__ float g_wp  [Esz*(size_t)HIDs];      // transposed small weight [N,K]
__device__ float g_wf1 [(size_t)FFs*HIDs];      // ffn1^T [4096,1024]
__device__ float g_wf2 [(size_t)FFs*HIDs];      // ffn2^T [1024,4096]

// ======================= helpers =============================================
__device__ __forceinline__ uint32_t smem_u32(const void* p) {
    uint32_t a;
    asm("{ .reg .u64 t; cvta.to.shared.u64 t, %1; cvt.u32.u64 %0, t; }"
        : "=r"(a) : "l"(p));
    return a;
}
__device__ __forceinline__ void cp16(uint32_t s, const void* g) {
    asm volatile("cp.async.cg.shared.global [%0], [%1], 16;"
                 :: "r"(s), "l"(g));
}
#define CP_COMMIT() asm volatile("cp.async.commit_group;" ::: "memory")
#define CP_WAIT(n)  asm volatile("cp.async.wait_group %0;" :: "n"(n) : "memory")

__device__ __forceinline__ uint32_t f2tf(float x) {
    uint32_t u;
    asm("cvt.rna.tf32.f32 %0, %1;" : "=r"(u) : "f"(x));
    return u;
}
__device__ __forceinline__ float tf32r(float x) {
    return __uint_as_float(f2tf(x));
}

// ======================= mma.sync tf32 GEMM ==================================
// C[M,N] = epi(A[M,K] @ Bt[N,K]^T + bias).  Bt row-major [N,K], pre-tf32.
// 256 threads: 8 warps, 2x4 grid of 64x32 warp tiles over a 128x128 CTA tile.
enum { EPI_BIAS = 0, EPI_TANH = 1, EPI_MUL = 2, EPI_GELU = 3, EPI_RES = 4 };

#define TGK   32                // k-chunk
#define TSTR  36                // smem row stride (floats): bank-bijective
#define TILEB 18432u            // 128*36*4 bytes per operand buffer
#define SMTOT 73728u            // 2 buffers * (A+B)

template <int EPI>
__global__ __launch_bounds__(256, 2)
void tgemm(const float* __restrict__ A, int lda,
           const float* __restrict__ Bt, int ldb,
           float* __restrict__ C, int ldc,
           const float* __restrict__ bias,
           const float* __restrict__ extra,
           int K)
{
    extern __shared__ char smem[];
    const uint32_t sb = smem_u32(smem);
    const int tid = threadIdx.x;
    const int wid = tid >> 5, lane = tid & 31;
    const int g = lane >> 2, tig = lane & 3;
    const int wm = wid >> 2, wn = wid & 3;       // 2x4 warps of 64x32
    const int m0 = blockIdx.y * 128, n0 = blockIdx.x * 128;

    const float* Ag = A  + (size_t)m0 * lda;
    const float* Bg = Bt + (size_t)n0 * ldb;

    const int NC = K / TGK;

    float acc[4][4][4];
    #pragma unroll
    for (int i = 0; i < 4; ++i)
        #pragma unroll
        for (int j = 0; j < 4; ++j)
            #pragma unroll
            for (int q = 0; q < 4; ++q) acc[i][j][q] = 0.f;

    // prologue: load chunk 0 into buffer 0 (A:1024 f4, B:1024 f4; 4 each/thread)
    {
        const uint32_t sA = sb, sB = sb + TILEB;
        #pragma unroll
        for (int i = 0; i < 4; ++i) {
            int idx = i * 256 + tid;
            int r = idx >> 3, c4 = idx & 7;
            uint32_t so = (uint32_t)(r * TSTR + c4 * 4) * 4u;
            cp16(sA + so, Ag + (size_t)r * lda + c4 * 4);
            cp16(sB + so, Bg + (size_t)r * ldb + c4 * 4);
        }
        CP_COMMIT();
    }

    for (int c = 0; c < NC; ++c) {
        if (c + 1 < NC) {
            const int k0 = (c + 1) * TGK;
            const uint32_t bo = ((c + 1) & 1) ? 2u * TILEB : 0u;
            const uint32_t sA = sb + bo, sB = sb + bo + TILEB;
            #pragma unroll
            for (int i = 0; i < 4; ++i) {
                int idx = i * 256 + tid;
                int r = idx >> 3, c4 = idx & 7;
                uint32_t so = (uint32_t)(r * TSTR + c4 * 4) * 4u;
                cp16(sA + so, Ag + (size_t)r * lda + k0 + c4 * 4);
                cp16(sB + so, Bg + (size_t)r * ldb + k0 + c4 * 4);
            }
            CP_COMMIT();
            CP_WAIT(1);
        } else {
            CP_WAIT(0);
        }
        __syncthreads();

        const uint32_t bo = (c & 1) ? 2u * TILEB : 0u;
        const float* As = (const float*)(smem + bo);
        const float* Bs = (const float*)(smem + bo + TILEB);

        #pragma unroll
        for (int kk = 0; kk < 4; ++kk) {
            const int ks = kk * 8;
            uint32_t af[4][4], bf[4][2];
            #pragma unroll
            for (int tm = 0; tm < 4; ++tm) {
                const int r = wm * 64 + tm * 16 + g;
                af[tm][0] = f2tf(As[r * TSTR + ks + tig]);
                af[tm][1] = f2tf(As[(r + 8) * TSTR + ks + tig]);
                af[tm][2] = f2tf(As[r * TSTR + ks + tig + 4]);
                af[tm][3] = f2tf(As[(r + 8) * TSTR + ks + tig + 4]);
            }
            #pragma unroll
            for (int tn = 0; tn < 4; ++tn) {
                const int rn = wn * 32 + tn * 8 + g;
                bf[tn][0] = __float_as_uint(Bs[rn * TSTR + ks + tig]);
                bf[tn][1] = __float_as_uint(Bs[rn * TSTR + ks + tig + 4]);
            }
            #pragma unroll
            for (int tm = 0; tm < 4; ++tm)
                #pragma unroll
                for (int tn = 0; tn < 4; ++tn)
                    asm volatile(
                        "mma.sync.aligned.m16n8k8.row.col.f32.tf32.tf32.f32 "
                        "{%0,%1,%2,%3}, {%4,%5,%6,%7}, {%8,%9}, {%0,%1,%2,%3};"
                        : "+f"(acc[tm][tn][0]), "+f"(acc[tm][tn][1]),
                          "+f"(acc[tm][tn][2]), "+f"(acc[tm][tn][3])
                        : "r"(af[tm][0]), "r"(af[tm][1]),
                          "r"(af[tm][2]), "r"(af[tm][3]),
                          "r"(bf[tn][0]), "r"(bf[tn][1]));
        }
        __syncthreads();
    }

    // epilogue
    const int nBase = n0 + wn * 32;
    const int mBase = m0 + wm * 64;
    float2 bv[4];
    #pragma unroll
    for (int tn = 0; tn < 4; ++tn)
        bv[tn] = *(const float2*)(bias + nBase + tn * 8 + 2 * tig);

    #pragma unroll
    for (int tm = 0; tm < 4; ++tm) {
        #pragma unroll
        for (int hf = 0; hf < 2; ++hf) {
            const int gm = mBase + tm * 16 + g + hf * 8;
            float* Crow = C + (size_t)gm * ldc + nBase;
            const float* Erow = (EPI == EPI_RES)
                ? (extra + (size_t)gm * ldc + nBase) : nullptr;
            #pragma unroll
            for (int tn = 0; tn < 4; ++tn) {
                float x0 = acc[tm][tn][hf * 2 + 0] + bv[tn].x;
                float x1 = acc[tm][tn][hf * 2 + 1] + bv[tn].y;
                if (EPI == EPI_TANH) {
                    x0 = tanhf(x0); x1 = tanhf(x1);
                } else if (EPI == EPI_GELU) {
                    const float s = 0.70710678118654752f;
                    x0 = 0.5f * x0 * (1.f + erff(x0 * s));
                    x1 = 0.5f * x1 * (1.f + erff(x1 * s));
                } else if (EPI == EPI_RES) {
                    const float2 e = *(const float2*)(Erow + tn * 8 + 2 * tig);
                    x0 += e.x; x1 += e.y;
                }
                float2 o; o.x = x0; o.y = x1;
                *(float2*)(Crow + tn * 8 + 2 * tig) = o;
            }
        }
    }
}

// ---------------- weight transposes (pre-round to tf32) ----------------------
// [H,E,DH] -> [N=H*DH, E]
__global__ void pack_wT(const float* __restrict__ W, float* __restrict__ out) {
    int t = blockIdx.x * 256 + threadIdx.x;
    int n = t >> 10;
    int e = t & 1023;
    int h = n >> 6, d = n & 63;
    out[(size_t)n * Esz + e] = tf32r(W[h * (Esz * DHsz) + e * DHsz + d]);
}
// [K,N] -> [N,K]
__global__ void transKN(const float* __restrict__ in, float* __restrict__ out,
                        int K, int N) {
    __shared__ float t[32][33];
    int k0 = blockIdx.y * 32, n0 = blockIdx.x * 32;
    int x = threadIdx.x, y = threadIdx.y;
    #pragma unroll
    for (int i = 0; i < 32; i += 8)
        t[y + i][x] = in[(size_t)(k0 + y + i) * N + n0 + x];
    __syncthreads();
    #pragma unroll
    for (int i = 0; i < 32; i += 8)
        out[(size_t)(n0 + y + i) * K + k0 + x] = tf32r(t[x][y + i]);
}

// ---------------- SIMT SGEMM (tiny per-head GEMM) ----------------------------
#define BM 128
#define BN 64
#define BK 16
#define TMt 8
#define TNt 4

template <int EPI>
__global__ __launch_bounds__(256)
void sgemm(const float* __restrict__ A, int lda, long long aZ,
           const float* __restrict__ Bm, int ldb, long long bZ,
           float* __restrict__ C, int ldc, long long cZ,
           const float* __restrict__ bias, long long biasZ,
           const float* __restrict__ extra, int lde, long long eZ,
           int K)
{
    A    += blockIdx.z * aZ;
    Bm   += blockIdx.z * bZ;
    C    += blockIdx.z * cZ;
    bias += blockIdx.z * biasZ;
    if (EPI == EPI_MUL || EPI == EPI_RES) extra += blockIdx.z * eZ;

    const int m0 = blockIdx.y * BM;
    const int n0 = blockIdx.x * BN;
    const int tid = threadIdx.x;
    const int tx = tid & 15;
    const int ty = tid >> 4;

    __shared__ float As[BK][BM + 4];
    __shared__ float Bs[BK][BN];

    float acc[TMt][TNt];
    #pragma unroll
    for (int i = 0; i < TMt; ++i)
        #pragma unroll
        for (int j = 0; j < TNt; ++j) acc[i][j] = 0.f;

    const float* Ag = A + (size_t)m0 * lda;
    const float* Bg = Bm + n0;

    for (int k0 = 0; k0 < K; k0 += BK) {
        #pragma unroll
        for (int i = 0; i < 2; ++i) {
            int f  = tid + i * 256;
            int m  = f >> 2;
            int kq = (f & 3) * 4;
            const float4 v = *(const float4*)(Ag + (size_t)m * lda + k0 + kq);
            As[kq + 0][m] = v.x;
            As[kq + 1][m] = v.y;
            As[kq + 2][m] = v.z;
            As[kq + 3][m] = v.w;
        }
        {
            int k = tid >> 4;
            int c = (tid & 15) * 4;
            *(float4*)&Bs[k][c] = *(const float4*)(Bg + (size_t)(k0 + k) * ldb + c);
        }
        __syncthreads();
        #pragma unroll
        for (int k = 0; k < BK; ++k) {
            float ar[TMt], br[TNt];
            #pragma unroll
            for (int i = 0; i < TMt; ++i) ar[i] = As[k][ty * TMt + i];
            #pragma unroll
            for (int j = 0; j < TNt; ++j) br[j] = Bs[k][tx * TNt + j];
            #pragma unroll
            for (int i = 0; i < TMt; ++i)
                #pragma unroll
                for (int j = 0; j < TNt; ++j)
                    acc[i][j] = fmaf(ar[i], br[j], acc[i][j]);
        }
        __syncthreads();
    }

    float bvv[TNt];
    #pragma unroll
    for (int j = 0; j < TNt; ++j) bvv[j] = bias[n0 + tx * TNt + j];

    #pragma unroll
    for (int i = 0; i < TMt; ++i) {
        int gm = m0 + ty * TMt + i;
        float4 o;
        float* op = &o.x;
        #pragma unroll
        for (int j = 0; j < TNt; ++j) {
            float x = acc[i][j] + bvv[j];
            if (EPI == EPI_TANH)      x = tanhf(x);
            else if (EPI == EPI_GELU) x = 0.5f * x * (1.0f + erff(x * 0.70710678118654752f));
            op[j] = x;
        }
        if (EPI == EPI_MUL) {
            const float4 e = *(const float4*)(extra + (size_t)gm * lde + n0 + tx * TNt);
            o.x *= e.x; o.y *= e.y; o.z *= e.z; o.w *= e.w;
        } else if (EPI == EPI_RES) {
            const float4 e = *(const float4*)(extra + (size_t)gm * lde + n0 + tx * TNt);
            o.x += e.x; o.y += e.y; o.z += e.z; o.w += e.w;
        }
        *(float4*)(C + (size_t)gm * ldc + n0 + tx * TNt) = o;
    }
}

// ---------------- affine recurrence scan over L ------------------------------
__global__ void scan_kernel(const float* __restrict__ A, float* __restrict__ Bv) {
    int idx = blockIdx.x * 256 + threadIdx.x;
    size_t off = (size_t)(idx >> 10) * ((size_t)Lsz * HIDs) + (idx & 1023);
    float h = 0.f;
    for (int l = 0; l < Lsz; l += 16) {
        float av[16], bvv[16];
        #pragma unroll
        for (int j = 0; j < 16; ++j) {
            av[j]  = A [off + (size_t)j * HIDs];
            bvv[j] = Bv[off + (size_t)j * HIDs];
        }
        #pragma unroll
        for (int j = 0; j < 16; ++j) {
            h = fmaf(av[j], h, bvv[j]);
            Bv[off + (size_t)j * HIDs] = h;
        }
        off += (size_t)16 * HIDs;
    }
}

// ---------------- u = z + LayerNorm(z) ---------------------------------------
__global__ __launch_bounds__(256)
void ln_kernel(const float* __restrict__ z, const float* __restrict__ gamma,
               const float* __restrict__ beta, float* __restrict__ u)
{
    int row = blockIdx.x;
    const float4* zr = (const float4*)(z + (size_t)row * HIDs);
    float4 v = zr[threadIdx.x];

    float s = v.x + v.y + v.z + v.w;
    float q = v.x * v.x + v.y * v.y + v.z * v.z + v.w * v.w;
    #pragma unroll
    for (int o = 16; o; o >>= 1) {
        s += __shfl_down_sync(0xffffffffu, s, o);
        q += __shfl_down_sync(0xffffffffu, q, o);
    }
    __shared__ float ss[8], sq[8];
    __shared__ float mu_s, rs_s;
    int w = threadIdx.x >> 5;
    if ((threadIdx.x & 31) == 0) { ss[w] = s; sq[w] = q; }
    __syncthreads();
    if (threadIdx.x == 0) {
        float S = 0.f, Q = 0.f;
        #pragma unroll
        for (int i = 0; i < 8; ++i) { S += ss[i]; Q += sq[i]; }
        float mu  = S * (1.0f / HIDs);
        float var = Q * (1.0f / HIDs) - mu * mu;
        mu_s = mu;
        rs_s = rsqrtf(var + 1e-5f);
    }
    __syncthreads();
    float mu = mu_s, rs = rs_s;

    float4 gg = ((const float4*)gamma)[threadIdx.x];
    float4 bb = ((const float4*)beta )[threadIdx.x];
    float4 o;
    o.x = v.x + (v.x - mu) * rs * gg.x + bb.x;
    o.y = v.y + (v.y - mu) * rs * gg.y + bb.y;
    o.z = v.z + (v.z - mu) * rs * gg.z + bb.z;
    o.w = v.w + (v.w - mu) * rs * gg.w + bb.w;
    ((float4*)(u + (size_t)row * HIDs))[threadIdx.x] = o;
}

// ---------------- launch ------------------------------------------------------
extern "C" void kernel_launch(void* const* d_in, const int* in_sizes, int n_in,
                              void* d_out, int out_size)
{
    const float* emb = (const float*)d_in[0];
    const float* Wa  = (const float*)d_in[1];
    const float* ba  = (const float*)d_in[2];
    const float* Wb  = (const float*)d_in[3];
    const float* bb  = (const float*)d_in[4];
    const float* WD  = (const float*)d_in[5];
    const float* bD  = (const float*)d_in[6];
    const float* WC  = (const float*)d_in[7];
    const float* bC  = (const float*)d_in[8];
    const float* f1w = (const float*)d_in[9];
    const float* f1b = (const float*)d_in[10];
    const float* f2w = (const float*)d_in[11];
    const float* f2b = (const float*)d_in[12];
    const float* pw  = (const float*)d_in[13];
    const float* pb  = (const float*)d_in[14];
    const float* lng = (const float*)d_in[15];
    const float* lnb = (const float*)d_in[16];
    float* out = (float*)d_out;

    float *pa, *pbuf, *pd, *pz, *pu, *pmid, *pv, *pwp, *pwf1, *pwf2;
    cudaGetSymbolAddress((void**)&pa,   g_a);
    cudaGetSymbolAddress((void**)&pbuf, g_b);
    cudaGetSymbolAddress((void**)&pd,   g_d);
    cudaGetSymbolAddress((void**)&pz,   g_z);
    cudaGetSymbolAddress((void**)&pu,   g_u);
    cudaGetSymbolAddress((void**)&pmid, g_mid);
    cudaGetSymbolAddress((void**)&pv,   g_v);
    cudaGetSymbolAddress((void**)&pwp,  g_wp);
    cudaGetSymbolAddress((void**)&pwf1, g_wf1);
    cudaGetSymbolAddress((void**)&pwf2, g_wf2);

    cudaFuncSetAttribute(tgemm<EPI_BIAS>, cudaFuncAttributeMaxDynamicSharedMemorySize, SMTOT);
    cudaFuncSetAttribute(tgemm<EPI_TANH>, cudaFuncAttributeMaxDynamicSharedMemorySize, SMTOT);
    cudaFuncSetAttribute(tgemm<EPI_GELU>, cudaFuncAttributeMaxDynamicSharedMemorySize, SMTOT);
    cudaFuncSetAttribute(tgemm<EPI_RES>,  cudaFuncAttributeMaxDynamicSharedMemorySize, SMTOT);

    dim3 blk(256);
    dim3 gP(HIDs / 128, Msz / 128);           // 8 x 64   (N=1024)
    dim3 gF1(FFs / 128, Msz / 128);           // 32 x 64  (N=4096)
    dim3 gHead(1, Msz / BM, Hh);

    // a = tanh(emb @ Wa + ba)
    pack_wT<<<4096, 256>>>(Wa, pwp);
    tgemm<EPI_TANH><<<gP, blk, SMTOT>>>(emb, Esz, pwp, Esz, pa, HIDs, ba, nullptr, Esz);
    // b = emb @ Wb + bb
    pack_wT<<<4096, 256>>>(Wb, pwp);
    tgemm<EPI_BIAS><<<gP, blk, SMTOT>>>(emb, Esz, pwp, Esz, pbuf, HIDs, bb, nullptr, Esz);
    // d = emb @ WD + bD
    pack_wT<<<4096, 256>>>(WD, pwp);
    tgemm<EPI_BIAS><<<gP, blk, SMTOT>>>(emb, Esz, pwp, Esz, pd, HIDs, bD, nullptr, Esz);

    // h: affine scan over L (in place on b)
    scan_kernel<<<16, 256>>>(pa, pbuf);

    // z = (h @ WC + bC) * d   per head (tiny block-diag GEMM, SIMT fp32)
    sgemm<EPI_MUL><<<gHead, dim3(256)>>>(pbuf, HIDs, 64,
                                   WC, DHsz, (long long)DHsz * DHsz,
                                   pz, HIDs, 64,
                                   bC, 64,
                                   pd, HIDs, 64, DHsz);

    // u = z + LN(z)
    ln_kernel<<<Msz, 256>>>(pz, lng, lnb, pu);

    // transposed + tf32-rounded FFN weights
    transKN<<<dim3(FFs / 32, HIDs / 32), dim3(32, 8)>>>(f1w, pwf1, HIDs, FFs);
    transKN<<<dim3(HIDs / 32, FFs / 32), dim3(32, 8)>>>(f2w, pwf2, FFs, HIDs);

    // mid = gelu(u @ ffn1_w + ffn1_b)
    tgemm<EPI_GELU><<<gF1, blk, SMTOT>>>(pu, HIDs, pwf1, HIDs, pmid, FFs, f1b, nullptr, HIDs);
    // v = mid @ ffn2_w + ffn2_b + u
    tgemm<EPI_RES><<<gP, blk, SMTOT>>>(pmid, FFs, pwf2, FFs, pv, HIDs, f2b, pu, FFs);

    // out = v @ proj_w + proj_b
    transKN<<<dim3(HIDs / 32, HIDs / 32), dim3(32, 8)>>>(pw, pwp, HIDs, HIDs);
    tgemm<EPI_BIAS><<<gP, blk, SMTOT>>>(pv, HIDs, pwp, HIDs, out, HIDs, pb, nullptr, HIDs);
}

// round 8
// speedup vs baseline: 1.6569x; 1.6569x over previous
#include <cuda_runtime.h>
#include <cstdint>
#include <math.h>

// Problem dims
#define Bsz   4
#define Lsz   2048
#define Esz   1024
#define Hh    16
#define DHsz  64
#define HIDs  1024
#define Msz   (Bsz*Lsz)     // 8192 rows
#define FFs   (4*HIDs)      // 4096

// ---------------- scratch (no allocs allowed -> __device__ globals) ----------
__device__ float g_a   [Msz*(size_t)HIDs];
__device__ float g_b   [Msz*(size_t)HIDs];      // b, becomes h after scan
__device__ float g_d   [Msz*(size_t)HIDs];
__device__ float g_z   [Msz*(size_t)HIDs];
__device__ float g_u   [Msz*(size_t)HIDs];
__device__ float g_mid [(size_t)Msz*FFs];
__device__ float g_v   [Msz*(size_t)HIDs];
__device__ float g_wp  [Esz*(size_t)HIDs];      // transposed proj weight [N,K]
__device__ float g_wp3 [3*(size_t)Esz*HIDs];    // packed a/b/d weights [3072,1024]
__device__ float g_wf1 [(size_t)FFs*HIDs];      // ffn1^T [4096,1024]
__device__ float g_wf2 [(size_t)FFs*HIDs];      // ffn2^T [1024,4096]

// ======================= helpers =============================================
__device__ __forceinline__ uint32_t smem_u32(const void* p) {
    uint32_t a;
    asm("{ .reg .u64 t; cvta.to.shared.u64 t, %1; cvt.u32.u64 %0, t; }"
        : "=r"(a) : "l"(p));
    return a;
}
__device__ __forceinline__ void cp16(uint32_t s, const void* g) {
    asm volatile("cp.async.cg.shared.global [%0], [%1], 16;"
                 :: "r"(s), "l"(g));
}
#define CP_COMMIT() asm volatile("cp.async.commit_group;" ::: "memory")
#define CP_WAIT(n)  asm volatile("cp.async.wait_group %0;" :: "n"(n) : "memory")

__device__ __forceinline__ uint32_t f2tf(float x) {
    uint32_t u;
    asm("cvt.rna.tf32.f32 %0, %1;" : "=r"(u) : "f"(x));
    return u;
}
__device__ __forceinline__ float tf32r(float x) {
    return __uint_as_float(f2tf(x));
}

// ======================= mma.sync tf32 GEMM ==================================
// C[M,N] = epi(A[M,K] @ Bt[N,K]^T + bias).  Bt row-major [N,K], pre-tf32.
// 128 threads: 2x2 warps of 64x64 (R3-proven geometry, ~214 regs, no spills).
// 3-stage cp.async ring, one __syncthreads per k-chunk.
enum { EPI_BIAS = 0, EPI_TANH = 1, EPI_GELU = 3, EPI_RES = 4, EPI_ABD = 5 };

#define TGK    32               // k-chunk
#define TSTR   36               // smem row stride (floats): bank-bijective
#define TILEB  18432u           // 128*36*4 bytes per operand per stage
#define STAGEB 36864u           // A+B per stage
#define SMTOT3 110592u          // 3 stages

#define LOAD_CHUNK(kk0, stg) do {                                            \
    const uint32_t sA_ = sb + (uint32_t)(stg) * STAGEB, sB_ = sA_ + TILEB;   \
    _Pragma("unroll")                                                        \
    for (int i_ = 0; i_ < 8; ++i_) {                                         \
        int idx_ = i_ * 128 + tid;                                           \
        int r_ = idx_ >> 3, c4_ = idx_ & 7;                                  \
        uint32_t so_ = (uint32_t)(r_ * TSTR + c4_ * 4) * 4u;                 \
        cp16(sA_ + so_, Ag + (size_t)r_ * lda + (kk0) + c4_ * 4);            \
        cp16(sB_ + so_, Bg + (size_t)r_ * ldb + (kk0) + c4_ * 4);            \
    }                                                                        \
    CP_COMMIT(); } while (0)

template <int EPI>
__global__ __launch_bounds__(128)
void tgemm(const float* __restrict__ A, int lda,
           const float* __restrict__ Bt, int ldb,
           float* __restrict__ C, int ldc,
           const float* __restrict__ bias,
           const float* __restrict__ extra,
           int K,
           float* __restrict__ C2, const float* __restrict__ b2,
           float* __restrict__ C3, const float* __restrict__ b3)
{
    extern __shared__ char smem[];
    const uint32_t sb = smem_u32(smem);
    const int tid = threadIdx.x;
    const int wid = tid >> 5, lane = tid & 31;
    const int g = lane >> 2, tig = lane & 3;
    const int wm = wid >> 1, wn = wid & 1;       // 2x2 warps of 64x64
    const int m0 = blockIdx.y * 128, n0 = blockIdx.x * 128;

    const float* Ag = A  + (size_t)m0 * lda;
    const float* Bg = Bt + (size_t)n0 * ldb;

    const int NC = K / TGK;                      // always >= 2 here

    float acc[4][8][4];
    #pragma unroll
    for (int i = 0; i < 4; ++i)
        #pragma unroll
        for (int j = 0; j < 8; ++j)
            #pragma unroll
            for (int q = 0; q < 4; ++q) acc[i][j][q] = 0.f;

    // prologue: stages 0 and 1
    LOAD_CHUNK(0, 0);
    LOAD_CHUNK(TGK, 1);

    int stg = 0;          // stage holding chunk c
    int stg2 = 2;         // stage to fill with chunk c+2
    for (int c = 0; c < NC; ++c) {
        if (c + 1 < NC) { CP_WAIT(1); } else { CP_WAIT(0); }
        __syncthreads();
        if (c + 2 < NC) {
            LOAD_CHUNK((c + 2) * TGK, stg2);
        }

        const char* base = smem + (uint32_t)stg * STAGEB;
        const float* As = (const float*)base;
        const float* Bs = (const float*)(base + TILEB);

        #pragma unroll
        for (int kk = 0; kk < 4; ++kk) {
            const int ks = kk * 8;
            uint32_t af[4][4], bf[8][2];
            #pragma unroll
            for (int tm = 0; tm < 4; ++tm) {
                const int r = wm * 64 + tm * 16 + g;
                af[tm][0] = f2tf(As[r * TSTR + ks + tig]);
                af[tm][1] = f2tf(As[(r + 8) * TSTR + ks + tig]);
                af[tm][2] = f2tf(As[r * TSTR + ks + tig + 4]);
                af[tm][3] = f2tf(As[(r + 8) * TSTR + ks + tig + 4]);
            }
            #pragma unroll
            for (int tn = 0; tn < 8; ++tn) {
                const int rn = wn * 64 + tn * 8 + g;
                bf[tn][0] = __float_as_uint(Bs[rn * TSTR + ks + tig]);
                bf[tn][1] = __float_as_uint(Bs[rn * TSTR + ks + tig + 4]);
            }
            #pragma unroll
            for (int tm = 0; tm < 4; ++tm)
                #pragma unroll
                for (int tn = 0; tn < 8; ++tn)
                    asm volatile(
                        "mma.sync.aligned.m16n8k8.row.col.f32.tf32.tf32.f32 "
                        "{%0,%1,%2,%3}, {%4,%5,%6,%7}, {%8,%9}, {%0,%1,%2,%3};"
                        : "+f"(acc[tm][tn][0]), "+f"(acc[tm][tn][1]),
                          "+f"(acc[tm][tn][2]), "+f"(acc[tm][tn][3])
                        : "r"(af[tm][0]), "r"(af[tm][1]),
                          "r"(af[tm][2]), "r"(af[tm][3]),
                          "r"(bf[tn][0]), "r"(bf[tn][1]));
        }
        stg  = (stg  == 2) ? 0 : stg  + 1;
        stg2 = (stg2 == 2) ? 0 : stg2 + 1;
    }

    // epilogue — resolve output / bias / op (ABD: select by n-range)
    float*       Cw = C;
    const float* bw = bias;
    int nloc = n0;
    bool do_tanh = (EPI == EPI_TANH);
    if (EPI == EPI_ABD) {
        const int which = n0 >> 10;
        Cw = (which == 0) ? C : (which == 1) ? C2 : C3;
        bw = (which == 0) ? bias : (which == 1) ? b2 : b3;
        nloc = n0 & 1023;
        do_tanh = (which == 0);
    }

    const int nBase = nloc + wn * 64;
    const int mBase = m0 + wm * 64;
    float2 bv[8];
    #pragma unroll
    for (int tn = 0; tn < 8; ++tn)
        bv[tn] = *(const float2*)(bw + nBase + tn * 8 + 2 * tig);

    #pragma unroll
    for (int tm = 0; tm < 4; ++tm) {
        #pragma unroll
        for (int hf = 0; hf < 2; ++hf) {
            const int gm = mBase + tm * 16 + g + hf * 8;
            float* Crow = Cw + (size_t)gm * ldc + nBase;
            const float* Erow = (EPI == EPI_RES)
                ? (extra + (size_t)gm * ldc + nBase) : nullptr;
            #pragma unroll
            for (int tn = 0; tn < 8; ++tn) {
                float x0 = acc[tm][tn][hf * 2 + 0] + bv[tn].x;
                float x1 = acc[tm][tn][hf * 2 + 1] + bv[tn].y;
                if (EPI == EPI_TANH || EPI == EPI_ABD) {
                    if (do_tanh) { x0 = tanhf(x0); x1 = tanhf(x1); }
                } else if (EPI == EPI_GELU) {
                    const float s = 0.70710678118654752f;
                    x0 = 0.5f * x0 * (1.f + erff(x0 * s));
                    x1 = 0.5f * x1 * (1.f + erff(x1 * s));
                } else if (EPI == EPI_RES) {
                    const float2 e = *(const float2*)(Erow + tn * 8 + 2 * tig);
                    x0 += e.x; x1 += e.y;
                }
                float2 o; o.x = x0; o.y = x1;
                *(float2*)(Crow + tn * 8 + 2 * tig) = o;
            }
        }
    }
}

// ---------------- weight packing (pre-round to tf32) -------------------------
// pack Wa/Wb/WD [H,E,DH] into one [3*N, E] = [3072, 1024] transposed buffer
__global__ void pack_wT3(const float* __restrict__ Wa,
                         const float* __restrict__ Wb,
                         const float* __restrict__ WD,
                         float* __restrict__ out) {
    int t = blockIdx.x * 256 + threadIdx.x;      // 0 .. 3M-1
    int n3 = t >> 10;
    int e  = t & 1023;
    int which = n3 >> 10;
    int n = n3 & 1023;
    int h = n >> 6, d = n & 63;
    const float* W = (which == 0) ? Wa : (which == 1) ? Wb : WD;
    out[(size_t)n3 * Esz + e] = tf32r(W[h * (Esz * DHsz) + e * DHsz + d]);
}
// [K,N] -> [N,K]
__global__ void transKN(const float* __restrict__ in, float* __restrict__ out,
                        int K, int N) {
    __shared__ float t[32][33];
    int k0 = blockIdx.y * 32, n0 = blockIdx.x * 32;
    int x = threadIdx.x, y = threadIdx.y;
    #pragma unroll
    for (int i = 0; i < 32; i += 8)
        t[y + i][x] = in[(size_t)(k0 + y + i) * N + n0 + x];
    __syncthreads();
    #pragma unroll
    for (int i = 0; i < 32; i += 8)
        out[(size_t)(n0 + y + i) * K + k0 + x] = tf32r(t[x][y + i]);
}

// ---------------- SIMT SGEMM (tiny per-head GEMM, fp32) ----------------------
#define BM 128
#define BN 64
#define BK 16
#define TMt 8
#define TNt 4

__global__ __launch_bounds__(256)
void sgemm_mul(const float* __restrict__ A, int lda, long long aZ,
               const float* __restrict__ Bm, int ldb, long long bZ,
               float* __restrict__ C, int ldc, long long cZ,
               const float* __restrict__ bias, long long biasZ,
               const float* __restrict__ extra, int lde, long long eZ,
               int K)
{
    A    += blockIdx.z * aZ;
    Bm   += blockIdx.z * bZ;
    C    += blockIdx.z * cZ;
    bias += blockIdx.z * biasZ;
    extra += blockIdx.z * eZ;

    const int m0 = blockIdx.y * BM;
    const int n0 = blockIdx.x * BN;
    const int tid = threadIdx.x;
    const int tx = tid & 15;
    const int ty = tid >> 4;

    __shared__ float As[BK][BM + 4];
    __shared__ float Bs[BK][BN];

    float acc[TMt][TNt];
    #pragma unroll
    for (int i = 0; i < TMt; ++i)
        #pragma unroll
        for (int j = 0; j < TNt; ++j) acc[i][j] = 0.f;

    const float* Ag = A + (size_t)m0 * lda;
    const float* Bg = Bm + n0;

    for (int k0 = 0; k0 < K; k0 += BK) {
        #pragma unroll
        for (int i = 0; i < 2; ++i) {
            int f  = tid + i * 256;
            int m  = f >> 2;
            int kq = (f & 3) * 4;
            const float4 v = *(const float4*)(Ag + (size_t)m * lda + k0 + kq);
            As[kq + 0][m] = v.x;
            As[kq + 1][m] = v.y;
            As[kq + 2][m] = v.z;
            As[kq + 3][m] = v.w;
        }
        {
            int k = tid >> 4;
            int c = (tid & 15) * 4;
            *(float4*)&Bs[k][c] = *(const float4*)(Bg + (size_t)(k0 + k) * ldb + c);
        }
        __syncthreads();
        #pragma unroll
        for (int k = 0; k < BK; ++k) {
            float ar[TMt], br[TNt];
            #pragma unroll
            for (int i = 0; i < TMt; ++i) ar[i] = As[k][ty * TMt + i];
            #pragma unroll
            for (int j = 0; j < TNt; ++j) br[j] = Bs[k][tx * TNt + j];
            #pragma unroll
            for (int i = 0; i < TMt; ++i)
                #pragma unroll
                for (int j = 0; j < TNt; ++j)
                    acc[i][j] = fmaf(ar[i], br[j], acc[i][j]);
        }
        __syncthreads();
    }

    float bvv[TNt];
    #pragma unroll
    for (int j = 0; j < TNt; ++j) bvv[j] = bias[n0 + tx * TNt + j];

    #pragma unroll
    for (int i = 0; i < TMt; ++i) {
        int gm = m0 + ty * TMt + i;
        float4 o;
        float* op = &o.x;
        #pragma unroll
        for (int j = 0; j < TNt; ++j) op[j] = acc[i][j] + bvv[j];
        const float4 e = *(const float4*)(extra + (size_t)gm * lde + n0 + tx * TNt);
        o.x *= e.x; o.y *= e.y; o.z *= e.z; o.w *= e.w;
        *(float4*)(C + (size_t)gm * ldc + n0 + tx * TNt) = o;
    }
}

// ---------------- affine recurrence scan over L ------------------------------
__global__ void scan_kernel(const float* __restrict__ A, float* __restrict__ Bv) {
    int idx = blockIdx.x * 256 + threadIdx.x;
    size_t off = (size_t)(idx >> 10) * ((size_t)Lsz * HIDs) + (idx & 1023);
    float h = 0.f;
    for (int l = 0; l < Lsz; l += 16) {
        float av[16], bvv[16];
        #pragma unroll
        for (int j = 0; j < 16; ++j) {
            av[j]  = A [off + (size_t)j * HIDs];
            bvv[j] = Bv[off + (size_t)j * HIDs];
        }
        #pragma unroll
        for (int j = 0; j < 16; ++j) {
            h = fmaf(av[j], h, bvv[j]);
            Bv[off + (size_t)j * HIDs] = h;
        }
        off += (size_t)16 * HIDs;
    }
}

// ---------------- u = z + LayerNorm(z) ---------------------------------------
__global__ __launch_bounds__(256)
void ln_kernel(const float* __restrict__ z, const float* __restrict__ gamma,
               const float* __restrict__ beta, float* __restrict__ u)
{
    int row = blockIdx.x;
    const float4* zr = (const float4*)(z + (size_t)row * HIDs);
    float4 v = zr[threadIdx.x];

    float s = v.x + v.y + v.z + v.w;
    float q = v.x * v.x + v.y * v.y + v.z * v.z + v.w * v.w;
    #pragma unroll
    for (int o = 16; o; o >>= 1) {
        s += __shfl_down_sync(0xffffffffu, s, o);
        q += __shfl_down_sync(0xffffffffu, q, o);
    }
    __shared__ float ss[8], sq[8];
    __shared__ float mu_s, rs_s;
    int w = threadIdx.x >> 5;
    if ((threadIdx.x & 31) == 0) { ss[w] = s; sq[w] = q; }
    __syncthreads();
    if (threadIdx.x == 0) {
        float S = 0.f, Q = 0.f;
        #pragma unroll
        for (int i = 0; i < 8; ++i) { S += ss[i]; Q += sq[i]; }
        float mu  = S * (1.0f / HIDs);
        float var = Q * (1.0f / HIDs) - mu * mu;
        mu_s = mu;
        rs_s = rsqrtf(var + 1e-5f);
    }
    __syncthreads();
    float mu = mu_s, rs = rs_s;

    float4 gg = ((const float4*)gamma)[threadIdx.x];
    float4 bb = ((const float4*)beta )[threadIdx.x];
    float4 o;
    o.x = v.x + (v.x - mu) * rs * gg.x + bb.x;
    o.y = v.y + (v.y - mu) * rs * gg.y + bb.y;
    o.z = v.z + (v.z - mu) * rs * gg.z + bb.z;
    o.w = v.w + (v.w - mu) * rs * gg.w + bb.w;
    ((float4*)(u + (size_t)row * HIDs))[threadIdx.x] = o;
}

// ---------------- launch ------------------------------------------------------
extern "C" void kernel_launch(void* const* d_in, const int* in_sizes, int n_in,
                              void* d_out, int out_size)
{
    const float* emb = (const float*)d_in[0];
    const float* Wa  = (const float*)d_in[1];
    const float* ba  = (const float*)d_in[2];
    const float* Wb  = (const float*)d_in[3];
    const float* bb  = (const float*)d_in[4];
    const float* WD  = (const float*)d_in[5];
    const float* bD  = (const float*)d_in[6];
    const float* WC  = (const float*)d_in[7];
    const float* bC  = (const float*)d_in[8];
    const float* f1w = (const float*)d_in[9];
    const float* f1b = (const float*)d_in[10];
    const float* f2w = (const float*)d_in[11];
    const float* f2b = (const float*)d_in[12];
    const float* pw  = (const float*)d_in[13];
    const float* pb  = (const float*)d_in[14];
    const float* lng = (const float*)d_in[15];
    const float* lnb = (const float*)d_in[16];
    float* out = (float*)d_out;

    float *pa, *pbuf, *pd, *pz, *pu, *pmid, *pv, *pwp, *pwp3, *pwf1, *pwf2;
    cudaGetSymbolAddress((void**)&pa,   g_a);
    cudaGetSymbolAddress((void**)&pbuf, g_b);
    cudaGetSymbolAddress((void**)&pd,   g_d);
    cudaGetSymbolAddress((void**)&pz,   g_z);
    cudaGetSymbolAddress((void**)&pu,   g_u);
    cudaGetSymbolAddress((void**)&pmid, g_mid);
    cudaGetSymbolAddress((void**)&pv,   g_v);
    cudaGetSymbolAddress((void**)&pwp,  g_wp);
    cudaGetSymbolAddress((void**)&pwp3, g_wp3);
    cudaGetSymbolAddress((void**)&pwf1, g_wf1);
    cudaGetSymbolAddress((void**)&pwf2, g_wf2);

    cudaFuncSetAttribute(tgemm<EPI_BIAS>, cudaFuncAttributeMaxDynamicSharedMemorySize, SMTOT3);
    cudaFuncSetAttribute(tgemm<EPI_ABD>,  cudaFuncAttributeMaxDynamicSharedMemorySize, SMTOT3);
    cudaFuncSetAttribute(tgemm<EPI_GELU>, cudaFuncAttributeMaxDynamicSharedMemorySize, SMTOT3);
    cudaFuncSetAttribute(tgemm<EPI_RES>,  cudaFuncAttributeMaxDynamicSharedMemorySize, SMTOT3);

    dim3 blk(128);
    dim3 gABD(3 * HIDs / 128, Msz / 128);     // 24 x 64  (N=3072)
    dim3 gP(HIDs / 128, Msz / 128);           // 8 x 64   (N=1024)
    dim3 gF1(FFs / 128, Msz / 128);           // 32 x 64  (N=4096)
    dim3 gHead(1, Msz / BM, Hh);

    // a = tanh(emb @ Wa + ba); b = emb @ Wb + bb; d = emb @ WD + bD — one launch
    pack_wT3<<<12288, 256>>>(Wa, Wb, WD, pwp3);
    tgemm<EPI_ABD><<<gABD, blk, SMTOT3>>>(emb, Esz, pwp3, Esz, pa, HIDs, ba,
                                          nullptr, Esz, pbuf, bb, pd, bD);

    // h: affine scan over L (in place on b)
    scan_kernel<<<16, 256>>>(pa, pbuf);

    // z = (h @ WC + bC) * d   per head (tiny block-diag GEMM, SIMT fp32)
    sgemm_mul<<<gHead, dim3(256)>>>(pbuf, HIDs, 64,
                                    WC, DHsz, (long long)DHsz * DHsz,
                                    pz, HIDs, 64,
                                    bC, 64,
                                    pd, HIDs, 64, DHsz);

    // u = z + LN(z)
    ln_kernel<<<Msz, 256>>>(pz, lng, lnb, pu);

    // transposed + tf32-rounded FFN weights
    transKN<<<dim3(FFs / 32, HIDs / 32), dim3(32, 8)>>>(f1w, pwf1, HIDs, FFs);
    transKN<<<dim3(HIDs / 32, FFs / 32), dim3(32, 8)>>>(f2w, pwf2, FFs, HIDs);

    // mid = gelu(u @ ffn1_w + ffn1_b)
    tgemm<EPI_GELU><<<gF1, blk, SMTOT3>>>(pu, HIDs, pwf1, HIDs, pmid, FFs, f1b,
                                          nullptr, HIDs, nullptr, nullptr, nullptr, nullptr);
    // v = mid @ ffn2_w + ffn2_b + u
    tgemm<EPI_RES><<<gP, blk, SMTOT3>>>(pmid, FFs, pwf2, FFs, pv, HIDs, f2b,
                                        pu, FFs, nullptr, nullptr, nullptr, nullptr);

    // out = v @ proj_w + proj_b
    transKN<<<dim3(HIDs / 32, HIDs / 32), dim3(32, 8)>>>(pw, pwp, HIDs, HIDs);
    tgemm<EPI_BIAS><<<gP, blk, SMTOT3>>>(pv, HIDs, pwp, HIDs, out, HIDs, pb,
                                         nullptr, HIDs, nullptr, nullptr, nullptr, nullptr);
}